// round 1
// baseline (speedup 1.0000x reference)
#include <cuda_runtime.h>
#include <cuda_bf16.h>
#include <math.h>

// Problem constants
#define BB       4
#define NN       16384
#define DD       512
#define HH       8
#define DK       64
#define DV       64
#define HID      2048
#define NTOK     (BB * NN)          // 65536
#define LN_EPS   1e-5f
#define ATTN_EPS 1e-6f

// ---------------------------------------------------------------------------
// Scratch (device globals — no allocation allowed)
// ---------------------------------------------------------------------------
__device__ float g_h   [(size_t)NTOK * DD];   // LN1 output
__device__ float g_pq  [(size_t)NTOK * DD];   // phi(q)
__device__ float g_pk  [(size_t)NTOK * DD];   // phi(k)
__device__ float g_v   [(size_t)NTOK * DD];   // v
__device__ float g_attn[(size_t)NTOK * DD];   // attention vectors (pre-Wo)
__device__ float g_hres[(size_t)NTOK * DD];   // h + attn
__device__ float g_h2  [(size_t)NTOK * DD];   // LN2 output
__device__ float g_act [(size_t)NTOK * HID];  // gelu(h2@W1+b1)
__device__ float g_kv  [BB * HH * DK * DV];   // [32][64][64]
__device__ float g_ksum[BB * HH * DK];        // [32][64]

// ---------------------------------------------------------------------------
// LayerNorm: one block (128 threads) per row of 512
// ---------------------------------------------------------------------------
__global__ __launch_bounds__(128)
void ln_kernel(const float* __restrict__ x, const float* __restrict__ g,
               const float* __restrict__ bta, float* __restrict__ out)
{
    __shared__ float red[4];
    size_t row = blockIdx.x;
    int t = threadIdx.x;
    int lane = t & 31, warp = t >> 5;

    float4 v = *(const float4*)(x + row * DD + t * 4);
    float s = v.x + v.y + v.z + v.w;
    #pragma unroll
    for (int o = 16; o; o >>= 1) s += __shfl_xor_sync(0xffffffffu, s, o);
    if (lane == 0) red[warp] = s;
    __syncthreads();
    float mean = (red[0] + red[1] + red[2] + red[3]) * (1.0f / DD);
    __syncthreads();

    float dx = v.x - mean, dy = v.y - mean, dz = v.z - mean, dw = v.w - mean;
    float q = dx * dx + dy * dy + dz * dz + dw * dw;
    #pragma unroll
    for (int o = 16; o; o >>= 1) q += __shfl_xor_sync(0xffffffffu, q, o);
    if (lane == 0) red[warp] = q;
    __syncthreads();
    float var = (red[0] + red[1] + red[2] + red[3]) * (1.0f / DD);
    float rs = rsqrtf(var + LN_EPS);

    float4 gv = *(const float4*)(g + t * 4);
    float4 bv = *(const float4*)(bta + t * 4);
    float4 o;
    o.x = dx * rs * gv.x + bv.x;
    o.y = dy * rs * gv.y + bv.y;
    o.z = dz * rs * gv.z + bv.z;
    o.w = dw * rs * gv.w + bv.w;
    *(float4*)(out + row * DD + t * 4) = o;
}

// ---------------------------------------------------------------------------
// GEMM: C[M,N] = A[M,K] @ B[K,N] + bias, fused epilogues
// 128x128 tile, BK=16, 256 threads, 8x8 per thread
// ---------------------------------------------------------------------------
#define EPI_BIAS 0
#define EPI_PHI  1   // elu(x)+1 = x>0 ? x+1 : exp(x)
#define EPI_GELU 2   // tanh-approx gelu (JAX default)
#define EPI_RES  3   // + resid

__device__ __forceinline__ float gelu_tanh(float x) {
    float x3 = x * x * x;
    return 0.5f * x * (1.0f + tanhf(0.7978845608028654f * (x + 0.044715f * x3)));
}

template<int EPI>
__global__ __launch_bounds__(256, 2)
void gemm_kernel(const float* __restrict__ A, const float* __restrict__ B,
                 const float* __restrict__ bias, const float* __restrict__ resid,
                 float* __restrict__ C, int M, int N, int K)
{
    __shared__ float As[16][132];   // padded to break store conflicts
    __shared__ float Bs[16][128];

    const int t  = threadIdx.x;
    const int tr = t >> 4;          // 0..15
    const int tc = t & 15;          // 0..15
    const int row0 = tr * 8, col0 = tc * 8;
    const int mbase = blockIdx.y * 128;
    const int nbase = blockIdx.x * 128;

    float c[8][8];
    #pragma unroll
    for (int i = 0; i < 8; i++)
        #pragma unroll
        for (int j = 0; j < 8; j++) c[i][j] = 0.0f;

    for (int k0 = 0; k0 < K; k0 += 16) {
        #pragma unroll
        for (int i = 0; i < 2; i++) {
            int idx = t + i * 256;                    // 0..511
            int ar = idx >> 2, ak = (idx & 3) * 4;    // A: 128 rows x 4 float4
            float4 av = *(const float4*)(A + (size_t)(mbase + ar) * K + k0 + ak);
            As[ak + 0][ar] = av.x;
            As[ak + 1][ar] = av.y;
            As[ak + 2][ar] = av.z;
            As[ak + 3][ar] = av.w;
            int bk = idx >> 5, bn = (idx & 31) * 4;   // B: 16 rows x 32 float4
            float4 bv = *(const float4*)(B + (size_t)(k0 + bk) * N + nbase + bn);
            *(float4*)(&Bs[bk][bn]) = bv;
        }
        __syncthreads();
        #pragma unroll
        for (int k = 0; k < 16; k++) {
            float a[8], b[8];
            *(float4*)(a)     = *(const float4*)(&As[k][row0]);
            *(float4*)(a + 4) = *(const float4*)(&As[k][row0 + 4]);
            *(float4*)(b)     = *(const float4*)(&Bs[k][col0]);
            *(float4*)(b + 4) = *(const float4*)(&Bs[k][col0 + 4]);
            #pragma unroll
            for (int i = 0; i < 8; i++)
                #pragma unroll
                for (int j = 0; j < 8; j++) c[i][j] += a[i] * b[j];
        }
        __syncthreads();
    }

    const float* biasn = bias + nbase + col0;
    #pragma unroll
    for (int i = 0; i < 8; i++) {
        size_t m = (size_t)(mbase + row0 + i);
        float* crow = C + m * N + nbase + col0;
        const float* rrow = (EPI == EPI_RES) ? (resid + m * N + nbase + col0) : nullptr;
        #pragma unroll
        for (int j = 0; j < 8; j += 4) {
            float4 bv = *(const float4*)(biasn + j);
            float4 r;
            r.x = c[i][j + 0] + bv.x;
            r.y = c[i][j + 1] + bv.y;
            r.z = c[i][j + 2] + bv.z;
            r.w = c[i][j + 3] + bv.w;
            if (EPI == EPI_PHI) {
                r.x = (r.x > 0.0f) ? r.x + 1.0f : __expf(0.0f) * expf(r.x);
                r.y = (r.y > 0.0f) ? r.y + 1.0f : expf(r.y);
                r.z = (r.z > 0.0f) ? r.z + 1.0f : expf(r.z);
                r.w = (r.w > 0.0f) ? r.w + 1.0f : expf(r.w);
            } else if (EPI == EPI_GELU) {
                r.x = gelu_tanh(r.x);
                r.y = gelu_tanh(r.y);
                r.z = gelu_tanh(r.z);
                r.w = gelu_tanh(r.w);
            } else if (EPI == EPI_RES) {
                float4 rv = *(const float4*)(rrow + j);
                r.x += rv.x; r.y += rv.y; r.z += rv.z; r.w += rv.w;
            }
            *(float4*)(crow + j) = r;
        }
    }
}

// ---------------------------------------------------------------------------
// Zero kv + ksum accumulators (must be inside the graph each replay)
// ---------------------------------------------------------------------------
__global__ void zero_acc_kernel()
{
    int idx = blockIdx.x * blockDim.x + threadIdx.x;
    const int NKV = BB * HH * DK * DV;      // 131072
    const int NKS = BB * HH * DK;           // 2048
    if (idx < NKV) g_kv[idx] = 0.0f;
    else if (idx < NKV + NKS) g_ksum[idx - NKV] = 0.0f;
}

// ---------------------------------------------------------------------------
// kv[b,h,d,m] = sum_n pk[b,n,h,d] * v[b,n,h,m];  ksum[b,h,d] = sum_n pk
// grid = (32 bh, N/KV_CHUNK); split-K atomics into fp32 accumulators
// ---------------------------------------------------------------------------
#define KV_CHUNK 2048
__global__ __launch_bounds__(256)
void kvred_kernel(const float* __restrict__ pk, const float* __restrict__ v)
{
    __shared__ float s_pk[8][64];
    __shared__ float s_v[8][64];
    const int bh = blockIdx.x;
    const int b  = bh >> 3, h = bh & 7;
    const int n0 = blockIdx.y * KV_CHUNK;
    const int t  = threadIdx.x;
    const int d0 = (t >> 4) * 4, m0 = (t & 15) * 4;

    float c[4][4];
    #pragma unroll
    for (int i = 0; i < 4; i++)
        #pragma unroll
        for (int j = 0; j < 4; j++) c[i][j] = 0.0f;
    float sk = 0.0f;

    const size_t base = (size_t)b * NN * DD + h * 64;
    for (int n = n0; n < n0 + KV_CHUNK; n += 8) {
        #pragma unroll
        for (int i = 0; i < 2; i++) {
            int idx = t + i * 256;          // 0..511
            int tt = idx >> 6, dd = idx & 63;
            size_t off = base + (size_t)(n + tt) * DD + dd;
            s_pk[tt][dd] = pk[off];
            s_v [tt][dd] = v[off];
        }
        __syncthreads();
        #pragma unroll
        for (int tt = 0; tt < 8; tt++) {
            float a[4], bb2[4];
            *(float4*)a   = *(const float4*)(&s_pk[tt][d0]);
            *(float4*)bb2 = *(const float4*)(&s_v[tt][m0]);
            #pragma unroll
            for (int i = 0; i < 4; i++)
                #pragma unroll
                for (int j = 0; j < 4; j++) c[i][j] += a[i] * bb2[j];
        }
        if (t < 64) {
            #pragma unroll
            for (int tt = 0; tt < 8; tt++) sk += s_pk[tt][t];
        }
        __syncthreads();
    }

    float* kvp = g_kv + (size_t)bh * (DK * DV);
    #pragma unroll
    for (int i = 0; i < 4; i++)
        #pragma unroll
        for (int j = 0; j < 4; j++)
            atomicAdd(&kvp[(d0 + i) * DV + m0 + j], c[i][j]);
    if (t < 64) atomicAdd(&g_ksum[bh * DK + t], sk);
}

// ---------------------------------------------------------------------------
// attn[b,n,h,m] = z * sum_d pq[b,n,h,d]*kv[b,h,d,m]; z = 1/(pq.ksum + eps)
// one block per token, one warp per head. kv tile (16 KB) lives in L1/L2.
// ---------------------------------------------------------------------------
__global__ __launch_bounds__(256)
void attn_kernel(const float* __restrict__ pq, float* __restrict__ out)
{
    size_t bn = blockIdx.x;             // 0..65535
    int b = (int)(bn >> 14);            // /NN
    int w = threadIdx.x >> 5, l = threadIdx.x & 31;
    int bh = b * HH + w;

    const float* qp = pq + bn * DD + w * 64;
    float2 q  = *(const float2*)(qp + 2 * l);
    float2 ks = *(const float2*)(g_ksum + bh * DK + 2 * l);
    float dot = q.x * ks.x + q.y * ks.y;
    #pragma unroll
    for (int o = 16; o; o >>= 1) dot += __shfl_xor_sync(0xffffffffu, dot, o);
    float z = 1.0f / (dot + ATTN_EPS);

    const float* kvp = g_kv + (size_t)bh * (DK * DV);
    float acc0 = 0.0f, acc1 = 0.0f;
    #pragma unroll
    for (int d = 0; d < 64; d++) {
        float qd = __shfl_sync(0xffffffffu, (d & 1) ? q.y : q.x, d >> 1);
        float2 kvv = *(const float2*)(kvp + d * DV + 2 * l);
        acc0 += qd * kvv.x;
        acc1 += qd * kvv.y;
    }
    float2 o = make_float2(acc0 * z, acc1 * z);
    *(float2*)(out + bn * DD + w * 64 + 2 * l) = o;
}

// ---------------------------------------------------------------------------
// Launch
// ---------------------------------------------------------------------------
extern "C" void kernel_launch(void* const* d_in, const int* in_sizes, int n_in,
                              void* d_out, int out_size)
{
    const float* x     = (const float*)d_in[0];
    const float* ln1_g = (const float*)d_in[1];
    const float* ln1_b = (const float*)d_in[2];
    const float* Wq    = (const float*)d_in[3];
    const float* bq    = (const float*)d_in[4];
    const float* Wk    = (const float*)d_in[5];
    const float* bk    = (const float*)d_in[6];
    const float* Wv    = (const float*)d_in[7];
    const float* bv    = (const float*)d_in[8];
    const float* Wo    = (const float*)d_in[9];
    const float* bo    = (const float*)d_in[10];
    const float* ln2_g = (const float*)d_in[11];
    const float* ln2_b = (const float*)d_in[12];
    const float* W1    = (const float*)d_in[13];
    const float* b1    = (const float*)d_in[14];
    const float* W2    = (const float*)d_in[15];
    const float* b2    = (const float*)d_in[16];
    float* out = (float*)d_out;

    float *p_h, *p_pq, *p_pk, *p_v, *p_attn, *p_hres, *p_h2, *p_act;
    cudaGetSymbolAddress((void**)&p_h,    g_h);
    cudaGetSymbolAddress((void**)&p_pq,   g_pq);
    cudaGetSymbolAddress((void**)&p_pk,   g_pk);
    cudaGetSymbolAddress((void**)&p_v,    g_v);
    cudaGetSymbolAddress((void**)&p_attn, g_attn);
    cudaGetSymbolAddress((void**)&p_hres, g_hres);
    cudaGetSymbolAddress((void**)&p_h2,   g_h2);
    cudaGetSymbolAddress((void**)&p_act,  g_act);

    // 1. LN1
    ln_kernel<<<NTOK, 128>>>(x, ln1_g, ln1_b, p_h);

    // 2-4. Q, K, V projections (phi fused for q,k)
    {
        dim3 grid(DD / 128, NTOK / 128);
        gemm_kernel<EPI_PHI ><<<grid, 256>>>(p_h, Wq, bq, nullptr, p_pq, NTOK, DD, DD);
        gemm_kernel<EPI_PHI ><<<grid, 256>>>(p_h, Wk, bk, nullptr, p_pk, NTOK, DD, DD);
        gemm_kernel<EPI_BIAS><<<grid, 256>>>(p_h, Wv, bv, nullptr, p_v,  NTOK, DD, DD);
    }

    // 5. zero accumulators
    zero_acc_kernel<<<(BB * HH * DK * DV + BB * HH * DK + 255) / 256, 256>>>();

    // 6. kv / ksum reduction
    {
        dim3 grid(BB * HH, NN / KV_CHUNK);
        kvred_kernel<<<grid, 256>>>(p_pk, p_v);
    }

    // 7. attention apply
    attn_kernel<<<NTOK, 256>>>(p_pq, p_attn);

    // 8. output projection + residual (h + attn)
    {
        dim3 grid(DD / 128, NTOK / 128);
        gemm_kernel<EPI_RES><<<grid, 256>>>(p_attn, Wo, bo, p_h, p_hres, NTOK, DD, DD);
    }

    // 9. LN2
    ln_kernel<<<NTOK, 128>>>(p_hres, ln2_g, ln2_b, p_h2);

    // 10. MLP up + gelu
    {
        dim3 grid(HID / 128, NTOK / 128);
        gemm_kernel<EPI_GELU><<<grid, 256>>>(p_h2, W1, b1, nullptr, p_act, NTOK, HID, DD);
    }

    // 11. MLP down + bias + residual (h2 + dense) -> out
    {
        dim3 grid(DD / 128, NTOK / 128);
        gemm_kernel<EPI_RES><<<grid, 256>>>(p_act, W2, b2, p_h2, out, NTOK, DD, HID);
    }
}

// round 3
// speedup vs baseline: 2.5583x; 2.5583x over previous
#include <cuda_runtime.h>
#include <cuda_bf16.h>
#include <math.h>
#include <stdint.h>

// Problem constants
#define BB       4
#define NN       16384
#define DD       512
#define HH       8
#define DK       64
#define DV       64
#define HID      2048
#define NTOK     (BB * NN)          // 65536
#define LN_EPS   1e-5f
#define ATTN_EPS 1e-6f

// ---------------------------------------------------------------------------
// Scratch (device globals — no allocation allowed)
// ---------------------------------------------------------------------------
__device__ float g_h   [(size_t)NTOK * DD];
__device__ float g_pq  [(size_t)NTOK * DD];
__device__ float g_pk  [(size_t)NTOK * DD];
__device__ float g_v   [(size_t)NTOK * DD];
__device__ float g_attn[(size_t)NTOK * DD];
__device__ float g_hres[(size_t)NTOK * DD];
__device__ float g_h2  [(size_t)NTOK * DD];
__device__ float g_act [(size_t)NTOK * HID];
__device__ float g_kv  [BB * HH * DK * DV];
__device__ float g_ksum[BB * HH * DK];
// transposed (K-major) weights, tf32-rounded
__device__ float g_wqt[DD * DD];
__device__ float g_wkt[DD * DD];
__device__ float g_wvt[DD * DD];
__device__ float g_wot[DD * DD];
__device__ float g_w1t[(size_t)HID * DD];
__device__ float g_w2t[(size_t)DD * HID];

// ---------------------------------------------------------------------------
// helpers
// ---------------------------------------------------------------------------
__device__ __forceinline__ uint32_t smem_u32(const void* p) {
    uint32_t a;
    asm("{ .reg .u64 t; cvta.to.shared.u64 t, %1; cvt.u32.u64 %0, t; }" : "=r"(a) : "l"(p));
    return a;
}
__device__ __forceinline__ float tf32r(float x) {
    float y;
    asm("cvt.rna.tf32.f32 %0, %1;" : "=f"(y) : "f"(x));
    return y;
}

#define CP_ASYNC16(dst_u32, src) \
    asm volatile("cp.async.cg.shared.global [%0], [%1], 16;" :: "r"(dst_u32), "l"(src))
#define CP_COMMIT() asm volatile("cp.async.commit_group;" ::: "memory")
#define CP_WAIT(n)  asm volatile("cp.async.wait_group %0;" :: "n"(n) : "memory")

__device__ __forceinline__ void mma_tf32_16n8k8(float c[4], uint32_t a0, uint32_t a1,
                                                uint32_t a2, uint32_t a3,
                                                uint32_t b0, uint32_t b1)
{
    asm volatile(
        "mma.sync.aligned.m16n8k8.row.col.f32.tf32.tf32.f32 "
        "{%0,%1,%2,%3}, {%4,%5,%6,%7}, {%8,%9}, {%0,%1,%2,%3};"
        : "+f"(c[0]), "+f"(c[1]), "+f"(c[2]), "+f"(c[3])
        : "r"(a0), "r"(a1), "r"(a2), "r"(a3), "r"(b0), "r"(b1));
}

// ---------------------------------------------------------------------------
// tensor-core GEMM via mma.sync tf32
// C[M,N] = A[M,K] @ Bt[N,K]^T + bias, fused epilogue
// tile 128x128, BK=32, 2-stage cp.async, 8 warps (2M x 4N), warp tile 64x32
// ---------------------------------------------------------------------------
#define EPI_BIAS 0
#define EPI_PHI  1
#define EPI_GELU 2
#define EPI_RES  3

#define BK      32
#define PADK    36                       // 32 + 4 pad (floats)
#define SA_FL   (128 * PADK)             // floats per A stage
#define SB_FL   (128 * PADK)
#define GEMM_SMEM ((2 * SA_FL + 2 * SB_FL) * 4)   // 73728 bytes

__device__ __forceinline__ float gelu_tanh(float x) {
    float x3 = x * x * x;
    return 0.5f * x * (1.0f + tanhf(0.7978845608028654f * (x + 0.044715f * x3)));
}

template<int EPI>
__global__ __launch_bounds__(256)
void mgemm_kernel(const float* __restrict__ A, const float* __restrict__ Bt,
                  const float* __restrict__ bias, const float* __restrict__ resid,
                  float* __restrict__ C, int N, int K)
{
    extern __shared__ float smem[];
    float* sA = smem;                    // [2][128][PADK]
    float* sB = smem + 2 * SA_FL;        // [2][128][PADK]

    const int tid  = threadIdx.x;
    const int lane = tid & 31;
    const int wid  = tid >> 5;
    const int warpM = wid & 1;           // 0..1 -> 64 rows each
    const int warpN = wid >> 1;          // 0..3 -> 32 cols each

    const int mbase = blockIdx.y * 128;
    const int nbase = blockIdx.x * 128;

    // load indices: 1024 float4 per (A|B) stage, 256 threads -> 4 each
    // linear = tid + i*256 : row = linear/8, col = (linear%8)*4
    const uint32_t sA_u = smem_u32(sA);
    const uint32_t sB_u = smem_u32(sB);

    float acc[4][4][4];
    #pragma unroll
    for (int i = 0; i < 4; i++)
        #pragma unroll
        for (int j = 0; j < 4; j++)
            #pragma unroll
            for (int r = 0; r < 4; r++) acc[i][j][r] = 0.0f;

    const int T = K / BK;

    auto load_stage = [&](int kt, int st) {
        const int k0 = kt * BK;
        #pragma unroll
        for (int i = 0; i < 4; i++) {
            int linear = tid + i * 256;
            int row = linear >> 3;
            int col = (linear & 7) * 4;
            uint32_t da = sA_u + (uint32_t)((st * SA_FL + row * PADK + col) * 4);
            CP_ASYNC16(da, A + (size_t)(mbase + row) * K + k0 + col);
            uint32_t db = sB_u + (uint32_t)((st * SB_FL + row * PADK + col) * 4);
            CP_ASYNC16(db, Bt + (size_t)(nbase + row) * K + k0 + col);
        }
    };

    load_stage(0, 0);
    CP_COMMIT();

    for (int kt = 0; kt < T; kt++) {
        if (kt + 1 < T) {
            load_stage(kt + 1, (kt + 1) & 1);
            CP_COMMIT();
            CP_WAIT(1);
        } else {
            CP_WAIT(0);
        }
        __syncthreads();

        const float* a_st = sA + (kt & 1) * SA_FL;
        const float* b_st = sB + (kt & 1) * SB_FL;
        const int q = lane >> 2, r4 = lane & 3;

        #pragma unroll
        for (int ks = 0; ks < 4; ks++) {
            const int kk = ks * 8;
            uint32_t afr[4][4];
            #pragma unroll
            for (int mt = 0; mt < 4; mt++) {
                const float* ap = a_st + (warpM * 64 + mt * 16 + q) * PADK + kk + r4;
                afr[mt][0] = __float_as_uint(ap[0]);
                afr[mt][1] = __float_as_uint(ap[8 * PADK]);
                afr[mt][2] = __float_as_uint(ap[4]);
                afr[mt][3] = __float_as_uint(ap[8 * PADK + 4]);
            }
            uint32_t bfr[4][2];
            #pragma unroll
            for (int nt = 0; nt < 4; nt++) {
                const float* bp = b_st + (warpN * 32 + nt * 8 + q) * PADK + kk + r4;
                bfr[nt][0] = __float_as_uint(bp[0]);
                bfr[nt][1] = __float_as_uint(bp[4]);
            }
            #pragma unroll
            for (int mt = 0; mt < 4; mt++)
                #pragma unroll
                for (int nt = 0; nt < 4; nt++)
                    mma_tf32_16n8k8(acc[mt][nt], afr[mt][0], afr[mt][1],
                                    afr[mt][2], afr[mt][3], bfr[nt][0], bfr[nt][1]);
        }
        __syncthreads();
    }

    // ---- epilogue ----
    const int q = lane >> 2, r4 = lane & 3;
    #pragma unroll
    for (int mt = 0; mt < 4; mt++) {
        #pragma unroll
        for (int nt = 0; nt < 4; nt++) {
            int col = nbase + warpN * 32 + nt * 8 + 2 * r4;
            float2 bv = *(const float2*)(bias + col);
            #pragma unroll
            for (int half = 0; half < 2; half++) {
                size_t row = (size_t)(mbase + warpM * 64 + mt * 16 + q + half * 8);
                float2 o;
                o.x = acc[mt][nt][half * 2 + 0] + bv.x;
                o.y = acc[mt][nt][half * 2 + 1] + bv.y;
                if (EPI == EPI_PHI) {
                    o.x = (o.x > 0.0f) ? o.x + 1.0f : expf(o.x);
                    o.y = (o.y > 0.0f) ? o.y + 1.0f : expf(o.y);
                    o.x = tf32r(o.x); o.y = tf32r(o.y);
                } else if (EPI == EPI_GELU) {
                    o.x = tf32r(gelu_tanh(o.x));
                    o.y = tf32r(gelu_tanh(o.y));
                } else if (EPI == EPI_RES) {
                    float2 rv = *(const float2*)(resid + row * N + col);
                    o.x += rv.x; o.y += rv.y;
                }
                *(float2*)(C + row * N + col) = o;
            }
        }
    }
}

// ---------------------------------------------------------------------------
// Weight transpose W[K,N] -> Wt[N,K], tf32-rounded
// ---------------------------------------------------------------------------
__global__ __launch_bounds__(256)
void transpose_kernel(const float* __restrict__ W, float* __restrict__ Wt, int K, int N)
{
    __shared__ float tile[32][33];
    int k0 = blockIdx.x * 32, n0 = blockIdx.y * 32;
    int tx = threadIdx.x, ty = threadIdx.y;     // 32 x 8
    #pragma unroll
    for (int i = 0; i < 32; i += 8)
        tile[ty + i][tx] = W[(size_t)(k0 + ty + i) * N + n0 + tx];
    __syncthreads();
    #pragma unroll
    for (int i = 0; i < 32; i += 8)
        Wt[(size_t)(n0 + ty + i) * K + k0 + tx] = tf32r(tile[tx][ty + i]);
}

// ---------------------------------------------------------------------------
// LayerNorm (tf32-rounded output: feeds GEMM A operands)
// ---------------------------------------------------------------------------
__global__ __launch_bounds__(128)
void ln_kernel(const float* __restrict__ x, const float* __restrict__ g,
               const float* __restrict__ bta, float* __restrict__ out)
{
    __shared__ float red[4];
    size_t row = blockIdx.x;
    int t = threadIdx.x;
    int lane = t & 31, warp = t >> 5;

    float4 v = *(const float4*)(x + row * DD + t * 4);
    float s = v.x + v.y + v.z + v.w;
    #pragma unroll
    for (int o = 16; o; o >>= 1) s += __shfl_xor_sync(0xffffffffu, s, o);
    if (lane == 0) red[warp] = s;
    __syncthreads();
    float mean = (red[0] + red[1] + red[2] + red[3]) * (1.0f / DD);
    __syncthreads();

    float dx = v.x - mean, dy = v.y - mean, dz = v.z - mean, dw = v.w - mean;
    float q = dx * dx + dy * dy + dz * dz + dw * dw;
    #pragma unroll
    for (int o = 16; o; o >>= 1) q += __shfl_xor_sync(0xffffffffu, q, o);
    if (lane == 0) red[warp] = q;
    __syncthreads();
    float var = (red[0] + red[1] + red[2] + red[3]) * (1.0f / DD);
    float rs = rsqrtf(var + LN_EPS);

    float4 gv = *(const float4*)(g + t * 4);
    float4 bv = *(const float4*)(bta + t * 4);
    float4 o;
    o.x = tf32r(dx * rs * gv.x + bv.x);
    o.y = tf32r(dy * rs * gv.y + bv.y);
    o.z = tf32r(dz * rs * gv.z + bv.z);
    o.w = tf32r(dw * rs * gv.w + bv.w);
    *(float4*)(out + row * DD + t * 4) = o;
}

// ---------------------------------------------------------------------------
// Zero kv + ksum accumulators
// ---------------------------------------------------------------------------
__global__ void zero_acc_kernel()
{
    int idx = blockIdx.x * blockDim.x + threadIdx.x;
    const int NKV = BB * HH * DK * DV;
    const int NKS = BB * HH * DK;
    if (idx < NKV) g_kv[idx] = 0.0f;
    else if (idx < NKV + NKS) g_ksum[idx - NKV] = 0.0f;
}

// ---------------------------------------------------------------------------
// kv[b,h,d,m] = sum_n pk[b,n,h,d] * v[b,n,h,m];  ksum = sum_n pk
// ---------------------------------------------------------------------------
#define KV_CHUNK 2048
__global__ __launch_bounds__(256)
void kvred_kernel(const float* __restrict__ pk, const float* __restrict__ v)
{
    __shared__ float s_pk[8][64];
    __shared__ float s_v[8][64];
    const int bh = blockIdx.x;
    const int b  = bh >> 3, h = bh & 7;
    const int n0 = blockIdx.y * KV_CHUNK;
    const int t  = threadIdx.x;
    const int d0 = (t >> 4) * 4, m0 = (t & 15) * 4;

    float c[4][4];
    #pragma unroll
    for (int i = 0; i < 4; i++)
        #pragma unroll
        for (int j = 0; j < 4; j++) c[i][j] = 0.0f;
    float sk = 0.0f;

    const size_t base = (size_t)b * NN * DD + h * 64;
    for (int n = n0; n < n0 + KV_CHUNK; n += 8) {
        #pragma unroll
        for (int i = 0; i < 2; i++) {
            int idx = t + i * 256;
            int tt = idx >> 6, dd = idx & 63;
            size_t off = base + (size_t)(n + tt) * DD + dd;
            s_pk[tt][dd] = pk[off];
            s_v [tt][dd] = v[off];
        }
        __syncthreads();
        #pragma unroll
        for (int tt = 0; tt < 8; tt++) {
            float a[4], b2[4];
            *(float4*)a  = *(const float4*)(&s_pk[tt][d0]);
            *(float4*)b2 = *(const float4*)(&s_v[tt][m0]);
            #pragma unroll
            for (int i = 0; i < 4; i++)
                #pragma unroll
                for (int j = 0; j < 4; j++) c[i][j] += a[i] * b2[j];
        }
        if (t < 64) {
            #pragma unroll
            for (int tt = 0; tt < 8; tt++) sk += s_pk[tt][t];
        }
        __syncthreads();
    }

    float* kvp = g_kv + (size_t)bh * (DK * DV);
    #pragma unroll
    for (int i = 0; i < 4; i++)
        #pragma unroll
        for (int j = 0; j < 4; j++)
            atomicAdd(&kvp[(d0 + i) * DV + m0 + j], c[i][j]);
    if (t < 64) atomicAdd(&g_ksum[bh * DK + t], sk);
}

// ---------------------------------------------------------------------------
// attention apply: block = 64 tokens x (b,h); smem mini-GEMM 64x64x64
// ---------------------------------------------------------------------------
__global__ __launch_bounds__(256)
void attn_kernel(const float* __restrict__ pq, float* __restrict__ out)
{
    __shared__ float s_kv[64 * 64];
    __shared__ float s_q[64][65];
    __shared__ float s_z[64];
    const int bh = blockIdx.y;
    const int b = bh >> 3, h = bh & 7;
    const int n0 = blockIdx.x << 6;
    const int t = threadIdx.x;

    const float* kvp = g_kv + (size_t)bh * 4096;
    #pragma unroll
    for (int i = 0; i < 16; i++) s_kv[t + i * 256] = kvp[t + i * 256];

    const size_t qbase = ((size_t)b * NN + n0) * DD + h * 64;
    #pragma unroll
    for (int i = 0; i < 16; i++) {
        int idx = t + i * 256;
        int r = idx >> 6, c = idx & 63;
        s_q[r][c] = pq[qbase + (size_t)r * DD + c];
    }
    __syncthreads();

    if (t < 64) {
        const float* ks = g_ksum + bh * 64;
        float dot = 0.0f;
        #pragma unroll
        for (int d = 0; d < 64; d++) dot += s_q[t][d] * ks[d];
        s_z[t] = 1.0f / (dot + ATTN_EPS);
    }
    __syncthreads();

    const int i4 = (t >> 4) << 2;
    const int j4 = (t & 15) << 2;
    float acc[4][4] = {};
    #pragma unroll
    for (int d = 0; d < 64; d++) {
        float bvec[4];
        *(float4*)bvec = *(const float4*)(&s_kv[d * 64 + j4]);
        #pragma unroll
        for (int r = 0; r < 4; r++) {
            float a = s_q[i4 + r][d];
            acc[r][0] += a * bvec[0];
            acc[r][1] += a * bvec[1];
            acc[r][2] += a * bvec[2];
            acc[r][3] += a * bvec[3];
        }
    }
    #pragma unroll
    for (int r = 0; r < 4; r++) {
        float z = s_z[i4 + r];
        float4 o;
        o.x = tf32r(acc[r][0] * z);
        o.y = tf32r(acc[r][1] * z);
        o.z = tf32r(acc[r][2] * z);
        o.w = tf32r(acc[r][3] * z);
        *(float4*)(out + ((size_t)b * NN + n0 + i4 + r) * DD + h * 64 + j4) = o;
    }
}

// ---------------------------------------------------------------------------
// Launch
// ---------------------------------------------------------------------------
extern "C" void kernel_launch(void* const* d_in, const int* in_sizes, int n_in,
                              void* d_out, int out_size)
{
    const float* x     = (const float*)d_in[0];
    const float* ln1_g = (const float*)d_in[1];
    const float* ln1_b = (const float*)d_in[2];
    const float* Wq    = (const float*)d_in[3];
    const float* bq    = (const float*)d_in[4];
    const float* Wk    = (const float*)d_in[5];
    const float* bk    = (const float*)d_in[6];
    const float* Wv    = (const float*)d_in[7];
    const float* bv    = (const float*)d_in[8];
    const float* Wo    = (const float*)d_in[9];
    const float* bo    = (const float*)d_in[10];
    const float* ln2_g = (const float*)d_in[11];
    const float* ln2_b = (const float*)d_in[12];
    const float* W1    = (const float*)d_in[13];
    const float* b1    = (const float*)d_in[14];
    const float* W2    = (const float*)d_in[15];
    const float* b2    = (const float*)d_in[16];
    float* out = (float*)d_out;

    float *p_h, *p_pq, *p_pk, *p_v, *p_attn, *p_hres, *p_h2, *p_act;
    float *p_wqt, *p_wkt, *p_wvt, *p_wot, *p_w1t, *p_w2t;
    cudaGetSymbolAddress((void**)&p_h,    g_h);
    cudaGetSymbolAddress((void**)&p_pq,   g_pq);
    cudaGetSymbolAddress((void**)&p_pk,   g_pk);
    cudaGetSymbolAddress((void**)&p_v,    g_v);
    cudaGetSymbolAddress((void**)&p_attn, g_attn);
    cudaGetSymbolAddress((void**)&p_hres, g_hres);
    cudaGetSymbolAddress((void**)&p_h2,   g_h2);
    cudaGetSymbolAddress((void**)&p_act,  g_act);
    cudaGetSymbolAddress((void**)&p_wqt,  g_wqt);
    cudaGetSymbolAddress((void**)&p_wkt,  g_wkt);
    cudaGetSymbolAddress((void**)&p_wvt,  g_wvt);
    cudaGetSymbolAddress((void**)&p_wot,  g_wot);
    cudaGetSymbolAddress((void**)&p_w1t,  g_w1t);
    cudaGetSymbolAddress((void**)&p_w2t,  g_w2t);

    cudaFuncSetAttribute(mgemm_kernel<EPI_PHI >, cudaFuncAttributeMaxDynamicSharedMemorySize, GEMM_SMEM);
    cudaFuncSetAttribute(mgemm_kernel<EPI_BIAS>, cudaFuncAttributeMaxDynamicSharedMemorySize, GEMM_SMEM);
    cudaFuncSetAttribute(mgemm_kernel<EPI_GELU>, cudaFuncAttributeMaxDynamicSharedMemorySize, GEMM_SMEM);
    cudaFuncSetAttribute(mgemm_kernel<EPI_RES >, cudaFuncAttributeMaxDynamicSharedMemorySize, GEMM_SMEM);

    // 0. weight transposes (tf32-rounded, K-major)
    transpose_kernel<<<dim3(DD / 32, DD / 32),  dim3(32, 8)>>>(Wq, p_wqt, DD, DD);
    transpose_kernel<<<dim3(DD / 32, DD / 32),  dim3(32, 8)>>>(Wk, p_wkt, DD, DD);
    transpose_kernel<<<dim3(DD / 32, DD / 32),  dim3(32, 8)>>>(Wv, p_wvt, DD, DD);
    transpose_kernel<<<dim3(DD / 32, DD / 32),  dim3(32, 8)>>>(Wo, p_wot, DD, DD);
    transpose_kernel<<<dim3(DD / 32, HID / 32), dim3(32, 8)>>>(W1, p_w1t, DD, HID);
    transpose_kernel<<<dim3(HID / 32, DD / 32), dim3(32, 8)>>>(W2, p_w2t, HID, DD);

    // 1. LN1
    ln_kernel<<<NTOK, 128>>>(x, ln1_g, ln1_b, p_h);

    // 2-4. Q, K, V projections (tensor cores; phi fused on q,k)
    {
        dim3 grid(DD / 128, NTOK / 128);
        mgemm_kernel<EPI_PHI ><<<grid, 256, GEMM_SMEM>>>(p_h, p_wqt, bq, nullptr, p_pq, DD, DD);
        mgemm_kernel<EPI_PHI ><<<grid, 256, GEMM_SMEM>>>(p_h, p_wkt, bk, nullptr, p_pk, DD, DD);
        mgemm_kernel<EPI_BIAS><<<grid, 256, GEMM_SMEM>>>(p_h, p_wvt, bv, nullptr, p_v,  DD, DD);
    }

    // 5. zero accumulators
    zero_acc_kernel<<<(BB * HH * DK * DV + BB * HH * DK + 255) / 256, 256>>>();

    // 6. kv / ksum reduction
    kvred_kernel<<<dim3(BB * HH, NN / KV_CHUNK), 256>>>(p_pk, p_v);

    // 7. attention apply
    attn_kernel<<<dim3(NN / 64, BB * HH), 256>>>(p_pq, p_attn);

    // 8. output projection + residual
    mgemm_kernel<EPI_RES><<<dim3(DD / 128, NTOK / 128), 256, GEMM_SMEM>>>(
        p_attn, p_wot, bo, p_h, p_hres, DD, DD);

    // 9. LN2
    ln_kernel<<<NTOK, 128>>>(p_hres, ln2_g, ln2_b, p_h2);

    // 10. MLP up + gelu
    mgemm_kernel<EPI_GELU><<<dim3(HID / 128, NTOK / 128), 256, GEMM_SMEM>>>(
        p_h2, p_w1t, b1, nullptr, p_act, HID, DD);

    // 11. MLP down + residual -> out
    mgemm_kernel<EPI_RES><<<dim3(DD / 128, NTOK / 128), 256, GEMM_SMEM>>>(
        p_act, p_w2t, b2, p_h2, out, DD, HID);
}

// round 4
// speedup vs baseline: 3.0060x; 1.1750x over previous
#include <cuda_runtime.h>
#include <cuda_bf16.h>
#include <math.h>
#include <stdint.h>

// Problem constants
#define BB       4
#define NN       16384
#define DD       512
#define HH       8
#define DK       64
#define DV       64
#define HID      2048
#define NTOK     (BB * NN)          // 65536
#define LN_EPS   1e-5f
#define ATTN_EPS 1e-6f

// ---------------------------------------------------------------------------
// Scratch (device globals — no allocation allowed)
// ---------------------------------------------------------------------------
__device__ float g_h   [(size_t)NTOK * DD];
__device__ float g_pq  [(size_t)NTOK * DD];
__device__ float g_pk  [(size_t)NTOK * DD];
__device__ float g_v   [(size_t)NTOK * DD];
__device__ float g_attn[(size_t)NTOK * DD];
__device__ float g_hres[(size_t)NTOK * DD];
__device__ float g_h2  [(size_t)NTOK * DD];
__device__ float g_act [(size_t)NTOK * HID];
__device__ float g_kv  [BB * HH * DK * DV];
__device__ float g_ksum[BB * HH * DK];
// transposed (K-major) weights, tf32-rounded
__device__ float g_wqt[DD * DD];
__device__ float g_wkt[DD * DD];
__device__ float g_wvt[DD * DD];
__device__ float g_wot[DD * DD];
__device__ float g_w1t[(size_t)HID * DD];
__device__ float g_w2t[(size_t)DD * HID];

// ---------------------------------------------------------------------------
// helpers
// ---------------------------------------------------------------------------
__device__ __forceinline__ uint32_t smem_u32(const void* p) {
    uint32_t a;
    asm("{ .reg .u64 t; cvta.to.shared.u64 t, %1; cvt.u32.u64 %0, t; }" : "=r"(a) : "l"(p));
    return a;
}
__device__ __forceinline__ float tf32r(float x) {
    float y;
    asm("cvt.rna.tf32.f32 %0, %1;" : "=f"(y) : "f"(x));
    return y;
}

#define CP_ASYNC16(dst_u32, src) \
    asm volatile("cp.async.cg.shared.global [%0], [%1], 16;" :: "r"(dst_u32), "l"(src))
#define CP_COMMIT() asm volatile("cp.async.commit_group;" ::: "memory")
#define CP_WAIT(n)  asm volatile("cp.async.wait_group %0;" :: "n"(n) : "memory")

__device__ __forceinline__ void mma_tf32_16n8k8(float c[4], uint32_t a0, uint32_t a1,
                                                uint32_t a2, uint32_t a3,
                                                uint32_t b0, uint32_t b1)
{
    asm volatile(
        "mma.sync.aligned.m16n8k8.row.col.f32.tf32.tf32.f32 "
        "{%0,%1,%2,%3}, {%4,%5,%6,%7}, {%8,%9}, {%0,%1,%2,%3};"
        : "+f"(c[0]), "+f"(c[1]), "+f"(c[2]), "+f"(c[3])
        : "r"(a0), "r"(a1), "r"(a2), "r"(a3), "r"(b0), "r"(b1));
}

// ---------------------------------------------------------------------------
// tensor-core GEMM via mma.sync tf32
// C[M,N] = A[M,K] @ Bt[N,K]^T + bias, fused epilogue
// tile 128x128, BK=32, 3-stage cp.async (1 barrier/iter), 8 warps (2M x 4N)
// ---------------------------------------------------------------------------
#define EPI_BIAS 0
#define EPI_PHI  1
#define EPI_GELU 2
#define EPI_RES  3

#define BK      32
#define PADK    36                       // 32 + 4 pad (floats)
#define SA_FL   (128 * PADK)             // floats per A stage
#define SB_FL   (128 * PADK)
#define NSTG    3
#define STG_FL  (SA_FL + SB_FL)
#define GEMM_SMEM (NSTG * STG_FL * 4)    // 110592 bytes

__device__ __forceinline__ float gelu_tanh(float x) {
    float x3 = x * x * x;
    return 0.5f * x * (1.0f + tanhf(0.7978845608028654f * (x + 0.044715f * x3)));
}

template<int EPI>
__global__ __launch_bounds__(256)
void mgemm_kernel(const float* __restrict__ A, const float* __restrict__ Bt,
                  const float* __restrict__ bias, const float* __restrict__ resid,
                  float* __restrict__ C, int N, int K)
{
    extern __shared__ float smem[];

    const int tid  = threadIdx.x;
    const int lane = tid & 31;
    const int wid  = tid >> 5;
    const int warpM = wid & 1;           // 0..1 -> 64 rows each
    const int warpN = wid >> 1;          // 0..3 -> 32 cols each

    const int mbase = blockIdx.y * 128;
    const int nbase = blockIdx.x * 128;

    const uint32_t s_u = smem_u32(smem);

    float acc[4][4][4];
    #pragma unroll
    for (int i = 0; i < 4; i++)
        #pragma unroll
        for (int j = 0; j < 4; j++)
            #pragma unroll
            for (int r = 0; r < 4; r++) acc[i][j][r] = 0.0f;

    const int T = K / BK;

    // per-thread load coords: linear = tid + i*256, row = linear/8, col = (linear%8)*4
    auto load_stage = [&](int kt, int st) {
        const int k0 = kt * BK;
        const uint32_t base = s_u + (uint32_t)(st * STG_FL * 4);
        #pragma unroll
        for (int i = 0; i < 4; i++) {
            int linear = tid + i * 256;
            int row = linear >> 3;
            int col = (linear & 7) * 4;
            CP_ASYNC16(base + (uint32_t)((row * PADK + col) * 4),
                       A + (size_t)(mbase + row) * K + k0 + col);
            CP_ASYNC16(base + (uint32_t)((SA_FL + row * PADK + col) * 4),
                       Bt + (size_t)(nbase + row) * K + k0 + col);
        }
    };

    load_stage(0, 0); CP_COMMIT();
    load_stage(1, 1); CP_COMMIT();

    const int q = lane >> 2, r4 = lane & 3;

    for (int kt = 0; kt < T; kt++) {
        CP_WAIT(1);
        __syncthreads();                 // stage kt%3 visible to all; stage kt-1 fully consumed

        if (kt + 2 < T) load_stage(kt + 2, (kt + 2) % NSTG);
        CP_COMMIT();

        const float* a_st = smem + (kt % NSTG) * STG_FL;
        const float* b_st = a_st + SA_FL;

        // software-pipelined fragment loads (double-buffered in registers)
        uint32_t afr[2][4][4];
        uint32_t bfr[2][4][2];

        auto load_frag = [&](int ks, int buf) {
            const int kk = ks * 8;
            #pragma unroll
            for (int mt = 0; mt < 4; mt++) {
                const float* ap = a_st + (warpM * 64 + mt * 16 + q) * PADK + kk + r4;
                afr[buf][mt][0] = __float_as_uint(ap[0]);
                afr[buf][mt][1] = __float_as_uint(ap[8 * PADK]);
                afr[buf][mt][2] = __float_as_uint(ap[4]);
                afr[buf][mt][3] = __float_as_uint(ap[8 * PADK + 4]);
            }
            #pragma unroll
            for (int nt = 0; nt < 4; nt++) {
                const float* bp = b_st + (warpN * 32 + nt * 8 + q) * PADK + kk + r4;
                bfr[buf][nt][0] = __float_as_uint(bp[0]);
                bfr[buf][nt][1] = __float_as_uint(bp[4]);
            }
        };

        load_frag(0, 0);
        #pragma unroll
        for (int ks = 0; ks < 4; ks++) {
            if (ks < 3) load_frag(ks + 1, (ks + 1) & 1);
            const int b = ks & 1;
            #pragma unroll
            for (int mt = 0; mt < 4; mt++)
                #pragma unroll
                for (int nt = 0; nt < 4; nt++)
                    mma_tf32_16n8k8(acc[mt][nt], afr[b][mt][0], afr[b][mt][1],
                                    afr[b][mt][2], afr[b][mt][3],
                                    bfr[b][nt][0], bfr[b][nt][1]);
        }
    }

    // ---- epilogue ----
    #pragma unroll
    for (int mt = 0; mt < 4; mt++) {
        #pragma unroll
        for (int nt = 0; nt < 4; nt++) {
            int col = nbase + warpN * 32 + nt * 8 + 2 * r4;
            float2 bv = *(const float2*)(bias + col);
            #pragma unroll
            for (int half = 0; half < 2; half++) {
                size_t row = (size_t)(mbase + warpM * 64 + mt * 16 + q + half * 8);
                float2 o;
                o.x = acc[mt][nt][half * 2 + 0] + bv.x;
                o.y = acc[mt][nt][half * 2 + 1] + bv.y;
                if (EPI == EPI_PHI) {
                    o.x = (o.x > 0.0f) ? o.x + 1.0f : expf(o.x);
                    o.y = (o.y > 0.0f) ? o.y + 1.0f : expf(o.y);
                    o.x = tf32r(o.x); o.y = tf32r(o.y);
                } else if (EPI == EPI_GELU) {
                    o.x = tf32r(gelu_tanh(o.x));
                    o.y = tf32r(gelu_tanh(o.y));
                } else if (EPI == EPI_RES) {
                    float2 rv = *(const float2*)(resid + row * N + col);
                    o.x += rv.x; o.y += rv.y;
                }
                *(float2*)(C + row * N + col) = o;
            }
        }
    }
}

// ---------------------------------------------------------------------------
// Weight transpose W[K,N] -> Wt[N,K], tf32-rounded
// ---------------------------------------------------------------------------
__global__ __launch_bounds__(256)
void transpose_kernel(const float* __restrict__ W, float* __restrict__ Wt, int K, int N)
{
    __shared__ float tile[32][33];
    int k0 = blockIdx.x * 32, n0 = blockIdx.y * 32;
    int tx = threadIdx.x, ty = threadIdx.y;     // 32 x 8
    #pragma unroll
    for (int i = 0; i < 32; i += 8)
        tile[ty + i][tx] = W[(size_t)(k0 + ty + i) * N + n0 + tx];
    __syncthreads();
    #pragma unroll
    for (int i = 0; i < 32; i += 8)
        Wt[(size_t)(n0 + ty + i) * K + k0 + tx] = tf32r(tile[tx][ty + i]);
}

// ---------------------------------------------------------------------------
// LayerNorm (tf32-rounded output: feeds GEMM A operands)
// ---------------------------------------------------------------------------
__global__ __launch_bounds__(128)
void ln_kernel(const float* __restrict__ x, const float* __restrict__ g,
               const float* __restrict__ bta, float* __restrict__ out)
{
    __shared__ float red[4];
    size_t row = blockIdx.x;
    int t = threadIdx.x;
    int lane = t & 31, warp = t >> 5;

    float4 v = *(const float4*)(x + row * DD + t * 4);
    float s = v.x + v.y + v.z + v.w;
    #pragma unroll
    for (int o = 16; o; o >>= 1) s += __shfl_xor_sync(0xffffffffu, s, o);
    if (lane == 0) red[warp] = s;
    __syncthreads();
    float mean = (red[0] + red[1] + red[2] + red[3]) * (1.0f / DD);
    __syncthreads();

    float dx = v.x - mean, dy = v.y - mean, dz = v.z - mean, dw = v.w - mean;
    float q = dx * dx + dy * dy + dz * dz + dw * dw;
    #pragma unroll
    for (int o = 16; o; o >>= 1) q += __shfl_xor_sync(0xffffffffu, q, o);
    if (lane == 0) red[warp] = q;
    __syncthreads();
    float var = (red[0] + red[1] + red[2] + red[3]) * (1.0f / DD);
    float rs = rsqrtf(var + LN_EPS);

    float4 gv = *(const float4*)(g + t * 4);
    float4 bv = *(const float4*)(bta + t * 4);
    float4 o;
    o.x = tf32r(dx * rs * gv.x + bv.x);
    o.y = tf32r(dy * rs * gv.y + bv.y);
    o.z = tf32r(dz * rs * gv.z + bv.z);
    o.w = tf32r(dw * rs * gv.w + bv.w);
    *(float4*)(out + row * DD + t * 4) = o;
}

// ---------------------------------------------------------------------------
// Zero kv + ksum accumulators
// ---------------------------------------------------------------------------
__global__ void zero_acc_kernel()
{
    int idx = blockIdx.x * blockDim.x + threadIdx.x;
    const int NKV = BB * HH * DK * DV;
    const int NKS = BB * HH * DK;
    if (idx < NKV) g_kv[idx] = 0.0f;
    else if (idx < NKV + NKS) g_ksum[idx - NKV] = 0.0f;
}

// ---------------------------------------------------------------------------
// kv[b,h,d,m] = sum_n pk[b,n,h,d] * v[b,n,h,m];  ksum = sum_n pk
// ---------------------------------------------------------------------------
#define KV_CHUNK 2048
__global__ __launch_bounds__(256)
void kvred_kernel(const float* __restrict__ pk, const float* __restrict__ v)
{
    __shared__ float s_pk[8][64];
    __shared__ float s_v[8][64];
    const int bh = blockIdx.x;
    const int b  = bh >> 3, h = bh & 7;
    const int n0 = blockIdx.y * KV_CHUNK;
    const int t  = threadIdx.x;
    const int d0 = (t >> 4) * 4, m0 = (t & 15) * 4;

    float c[4][4];
    #pragma unroll
    for (int i = 0; i < 4; i++)
        #pragma unroll
        for (int j = 0; j < 4; j++) c[i][j] = 0.0f;
    float sk = 0.0f;

    const size_t base = (size_t)b * NN * DD + h * 64;
    for (int n = n0; n < n0 + KV_CHUNK; n += 8) {
        #pragma unroll
        for (int i = 0; i < 2; i++) {
            int idx = t + i * 256;
            int tt = idx >> 6, dd = idx & 63;
            size_t off = base + (size_t)(n + tt) * DD + dd;
            s_pk[tt][dd] = pk[off];
            s_v [tt][dd] = v[off];
        }
        __syncthreads();
        #pragma unroll
        for (int tt = 0; tt < 8; tt++) {
            float a[4], b2[4];
            *(float4*)a  = *(const float4*)(&s_pk[tt][d0]);
            *(float4*)b2 = *(const float4*)(&s_v[tt][m0]);
            #pragma unroll
            for (int i = 0; i < 4; i++)
                #pragma unroll
                for (int j = 0; j < 4; j++) c[i][j] += a[i] * b2[j];
        }
        if (t < 64) {
            #pragma unroll
            for (int tt = 0; tt < 8; tt++) sk += s_pk[tt][t];
        }
        __syncthreads();
    }

    float* kvp = g_kv + (size_t)bh * (DK * DV);
    #pragma unroll
    for (int i = 0; i < 4; i++)
        #pragma unroll
        for (int j = 0; j < 4; j++)
            atomicAdd(&kvp[(d0 + i) * DV + m0 + j], c[i][j]);
    if (t < 64) atomicAdd(&g_ksum[bh * DK + t], sk);
}

// ---------------------------------------------------------------------------
// attention apply: block = 64 tokens x (b,h); smem mini-GEMM 64x64x64
// ---------------------------------------------------------------------------
__global__ __launch_bounds__(256)
void attn_kernel(const float* __restrict__ pq, float* __restrict__ out)
{
    __shared__ float s_kv[64 * 64];
    __shared__ float s_q[64][65];
    __shared__ float s_z[64];
    const int bh = blockIdx.y;
    const int b = bh >> 3, h = bh & 7;
    const int n0 = blockIdx.x << 6;
    const int t = threadIdx.x;

    const float* kvp = g_kv + (size_t)bh * 4096;
    #pragma unroll
    for (int i = 0; i < 16; i++) s_kv[t + i * 256] = kvp[t + i * 256];

    const size_t qbase = ((size_t)b * NN + n0) * DD + h * 64;
    #pragma unroll
    for (int i = 0; i < 16; i++) {
        int idx = t + i * 256;
        int r = idx >> 6, c = idx & 63;
        s_q[r][c] = pq[qbase + (size_t)r * DD + c];
    }
    __syncthreads();

    if (t < 64) {
        const float* ks = g_ksum + bh * 64;
        float dot = 0.0f;
        #pragma unroll
        for (int d = 0; d < 64; d++) dot += s_q[t][d] * ks[d];
        s_z[t] = 1.0f / (dot + ATTN_EPS);
    }
    __syncthreads();

    const int i4 = (t >> 4) << 2;
    const int j4 = (t & 15) << 2;
    float acc[4][4] = {};
    #pragma unroll
    for (int d = 0; d < 64; d++) {
        float bvec[4];
        *(float4*)bvec = *(const float4*)(&s_kv[d * 64 + j4]);
        #pragma unroll
        for (int r = 0; r < 4; r++) {
            float a = s_q[i4 + r][d];
            acc[r][0] += a * bvec[0];
            acc[r][1] += a * bvec[1];
            acc[r][2] += a * bvec[2];
            acc[r][3] += a * bvec[3];
        }
    }
    #pragma unroll
    for (int r = 0; r < 4; r++) {
        float z = s_z[i4 + r];
        float4 o;
        o.x = tf32r(acc[r][0] * z);
        o.y = tf32r(acc[r][1] * z);
        o.z = tf32r(acc[r][2] * z);
        o.w = tf32r(acc[r][3] * z);
        *(float4*)(out + ((size_t)b * NN + n0 + i4 + r) * DD + h * 64 + j4) = o;
    }
}

// ---------------------------------------------------------------------------
// Launch
// ---------------------------------------------------------------------------
extern "C" void kernel_launch(void* const* d_in, const int* in_sizes, int n_in,
                              void* d_out, int out_size)
{
    const float* x     = (const float*)d_in[0];
    const float* ln1_g = (const float*)d_in[1];
    const float* ln1_b = (const float*)d_in[2];
    const float* Wq    = (const float*)d_in[3];
    const float* bq    = (const float*)d_in[4];
    const float* Wk    = (const float*)d_in[5];
    const float* bk    = (const float*)d_in[6];
    const float* Wv    = (const float*)d_in[7];
    const float* bv    = (const float*)d_in[8];
    const float* Wo    = (const float*)d_in[9];
    const float* bo    = (const float*)d_in[10];
    const float* ln2_g = (const float*)d_in[11];
    const float* ln2_b = (const float*)d_in[12];
    const float* W1    = (const float*)d_in[13];
    const float* b1    = (const float*)d_in[14];
    const float* W2    = (const float*)d_in[15];
    const float* b2    = (const float*)d_in[16];
    float* out = (float*)d_out;

    float *p_h, *p_pq, *p_pk, *p_v, *p_attn, *p_hres, *p_h2, *p_act;
    float *p_wqt, *p_wkt, *p_wvt, *p_wot, *p_w1t, *p_w2t;
    cudaGetSymbolAddress((void**)&p_h,    g_h);
    cudaGetSymbolAddress((void**)&p_pq,   g_pq);
    cudaGetSymbolAddress((void**)&p_pk,   g_pk);
    cudaGetSymbolAddress((void**)&p_v,    g_v);
    cudaGetSymbolAddress((void**)&p_attn, g_attn);
    cudaGetSymbolAddress((void**)&p_hres, g_hres);
    cudaGetSymbolAddress((void**)&p_h2,   g_h2);
    cudaGetSymbolAddress((void**)&p_act,  g_act);
    cudaGetSymbolAddress((void**)&p_wqt,  g_wqt);
    cudaGetSymbolAddress((void**)&p_wkt,  g_wkt);
    cudaGetSymbolAddress((void**)&p_wvt,  g_wvt);
    cudaGetSymbolAddress((void**)&p_wot,  g_wot);
    cudaGetSymbolAddress((void**)&p_w1t,  g_w1t);
    cudaGetSymbolAddress((void**)&p_w2t,  g_w2t);

    cudaFuncSetAttribute(mgemm_kernel<EPI_PHI >, cudaFuncAttributeMaxDynamicSharedMemorySize, GEMM_SMEM);
    cudaFuncSetAttribute(mgemm_kernel<EPI_BIAS>, cudaFuncAttributeMaxDynamicSharedMemorySize, GEMM_SMEM);
    cudaFuncSetAttribute(mgemm_kernel<EPI_GELU>, cudaFuncAttributeMaxDynamicSharedMemorySize, GEMM_SMEM);
    cudaFuncSetAttribute(mgemm_kernel<EPI_RES >, cudaFuncAttributeMaxDynamicSharedMemorySize, GEMM_SMEM);

    // 0. weight transposes (tf32-rounded, K-major)
    transpose_kernel<<<dim3(DD / 32, DD / 32),  dim3(32, 8)>>>(Wq, p_wqt, DD, DD);
    transpose_kernel<<<dim3(DD / 32, DD / 32),  dim3(32, 8)>>>(Wk, p_wkt, DD, DD);
    transpose_kernel<<<dim3(DD / 32, DD / 32),  dim3(32, 8)>>>(Wv, p_wvt, DD, DD);
    transpose_kernel<<<dim3(DD / 32, DD / 32),  dim3(32, 8)>>>(Wo, p_wot, DD, DD);
    transpose_kernel<<<dim3(DD / 32, HID / 32), dim3(32, 8)>>>(W1, p_w1t, DD, HID);
    transpose_kernel<<<dim3(HID / 32, DD / 32), dim3(32, 8)>>>(W2, p_w2t, HID, DD);

    // 1. LN1
    ln_kernel<<<NTOK, 128>>>(x, ln1_g, ln1_b, p_h);

    // 2-4. Q, K, V projections (tensor cores; phi fused on q,k)
    {
        dim3 grid(DD / 128, NTOK / 128);
        mgemm_kernel<EPI_PHI ><<<grid, 256, GEMM_SMEM>>>(p_h, p_wqt, bq, nullptr, p_pq, DD, DD);
        mgemm_kernel<EPI_PHI ><<<grid, 256, GEMM_SMEM>>>(p_h, p_wkt, bk, nullptr, p_pk, DD, DD);
        mgemm_kernel<EPI_BIAS><<<grid, 256, GEMM_SMEM>>>(p_h, p_wvt, bv, nullptr, p_v,  DD, DD);
    }

    // 5. zero accumulators
    zero_acc_kernel<<<(BB * HH * DK * DV + BB * HH * DK + 255) / 256, 256>>>();

    // 6. kv / ksum reduction
    kvred_kernel<<<dim3(BB * HH, NN / KV_CHUNK), 256>>>(p_pk, p_v);

    // 7. attention apply
    attn_kernel<<<dim3(NN / 64, BB * HH), 256>>>(p_pq, p_attn);

    // 8. output projection + residual
    mgemm_kernel<EPI_RES><<<dim3(DD / 128, NTOK / 128), 256, GEMM_SMEM>>>(
        p_attn, p_wot, bo, p_h, p_hres, DD, DD);

    // 9. LN2
    ln_kernel<<<NTOK, 128>>>(p_hres, ln2_g, ln2_b, p_h2);

    // 10. MLP up + gelu
    mgemm_kernel<EPI_GELU><<<dim3(HID / 128, NTOK / 128), 256, GEMM_SMEM>>>(
        p_h2, p_w1t, b1, nullptr, p_act, HID, DD);

    // 11. MLP down + residual -> out
    mgemm_kernel<EPI_RES><<<dim3(DD / 128, NTOK / 128), 256, GEMM_SMEM>>>(
        p_act, p_w2t, b2, p_h2, out, DD, HID);
}

// round 5
// speedup vs baseline: 4.8382x; 1.6095x over previous
#include <cuda_runtime.h>
#include <cuda_fp16.h>
#include <math.h>
#include <stdint.h>

// Problem constants
#define BB       4
#define NN       16384
#define DD       512
#define HH       8
#define DK       64
#define DV       64
#define HID      2048
#define NTOK     (BB * NN)          // 65536
#define LN_EPS   1e-5f
#define ATTN_EPS 1e-6f

// ---------------------------------------------------------------------------
// Scratch (device globals — no allocation allowed)
// ---------------------------------------------------------------------------
__device__ __half g_h   [(size_t)NTOK * DD];   // LN1 out (GEMM A + residual)
__device__ __half g_pq  [(size_t)NTOK * DD];
__device__ __half g_pk  [(size_t)NTOK * DD];
__device__ __half g_v   [(size_t)NTOK * DD];
__device__ __half g_attn[(size_t)NTOK * DD];
__device__ float  g_hres[(size_t)NTOK * DD];   // h + attn (fp32, feeds LN2)
__device__ __half g_h2  [(size_t)NTOK * DD];
__device__ __half g_act [(size_t)NTOK * HID];
__device__ float  g_kv  [BB * HH * DK * DV];
__device__ float  g_ksum[BB * HH * DK];
// transposed (K-major) fp16 weights
__device__ __half g_wqt[DD * DD];
__device__ __half g_wkt[DD * DD];
__device__ __half g_wvt[DD * DD];
__device__ __half g_wot[DD * DD];
__device__ __half g_w1t[(size_t)HID * DD];
__device__ __half g_w2t[(size_t)DD * HID];

// ---------------------------------------------------------------------------
// helpers
// ---------------------------------------------------------------------------
__device__ __forceinline__ uint32_t smem_u32(const void* p) {
    uint32_t a;
    asm("{ .reg .u64 t; cvta.to.shared.u64 t, %1; cvt.u32.u64 %0, t; }" : "=r"(a) : "l"(p));
    return a;
}

#define CP_ASYNC16(dst_u32, src) \
    asm volatile("cp.async.cg.shared.global [%0], [%1], 16;" :: "r"(dst_u32), "l"(src))
#define CP_COMMIT() asm volatile("cp.async.commit_group;" ::: "memory")
#define CP_WAIT(n)  asm volatile("cp.async.wait_group %0;" :: "n"(n) : "memory")

__device__ __forceinline__ void mma_f16_16n8k16(float c[4], uint32_t a0, uint32_t a1,
                                                uint32_t a2, uint32_t a3,
                                                uint32_t b0, uint32_t b1)
{
    asm volatile(
        "mma.sync.aligned.m16n8k16.row.col.f32.f16.f16.f32 "
        "{%0,%1,%2,%3}, {%4,%5,%6,%7}, {%8,%9}, {%0,%1,%2,%3};"
        : "+f"(c[0]), "+f"(c[1]), "+f"(c[2]), "+f"(c[3])
        : "r"(a0), "r"(a1), "r"(a2), "r"(a3), "r"(b0), "r"(b1));
}

// ---------------------------------------------------------------------------
// fp16 tensor-core GEMM: C[M,N] = A[M,K] @ Bt[N,K]^T + bias, fused epilogue
// tile 128x128, BK=64 halfs, 3-stage cp.async, 8 warps (2M x 4N)
// ---------------------------------------------------------------------------
#define EPI_BIAS 0
#define EPI_PHI  1
#define EPI_GELU 2
#define EPI_RES  3

#define BK      64
#define PADK    72                       // 64 + 8 pad (halfs)
#define SA_H    (128 * PADK)             // halfs per A stage
#define STG_H   (2 * SA_H)               // A + B
#define NSTG    3
#define GEMM_SMEM (NSTG * STG_H * 2)     // 110592 bytes

__device__ __forceinline__ float gelu_tanh(float x) {
    float x3 = x * x * x;
    return 0.5f * x * (1.0f + tanhf(0.7978845608028654f * (x + 0.044715f * x3)));
}

template<int EPI, typename CT>
__global__ __launch_bounds__(256)
void mgemm_kernel(const __half* __restrict__ A, const __half* __restrict__ Bt,
                  const float* __restrict__ bias, const __half* __restrict__ resid,
                  CT* __restrict__ C, int N, int K)
{
    extern __shared__ __half smem_h[];

    const int tid  = threadIdx.x;
    const int lane = tid & 31;
    const int wid  = tid >> 5;
    const int warpM = wid & 1;           // 0..1 -> 64 rows each
    const int warpN = wid >> 1;          // 0..3 -> 32 cols each

    const int mbase = blockIdx.y * 128;
    const int nbase = blockIdx.x * 128;

    const uint32_t s_u = smem_u32(smem_h);

    float acc[4][4][4];
    #pragma unroll
    for (int i = 0; i < 4; i++)
        #pragma unroll
        for (int j = 0; j < 4; j++)
            #pragma unroll
            for (int r = 0; r < 4; r++) acc[i][j][r] = 0.0f;

    const int T = K / BK;

    // per-thread load coords: linear = tid + i*256 (0..1023):
    // row = linear/8 (0..127), col = (linear%8)*8 halfs
    auto load_stage = [&](int kt, int st) {
        const int k0 = kt * BK;
        const uint32_t base = s_u + (uint32_t)(st * STG_H * 2);
        #pragma unroll
        for (int i = 0; i < 4; i++) {
            int linear = tid + i * 256;
            int row = linear >> 3;
            int col = (linear & 7) * 8;
            CP_ASYNC16(base + (uint32_t)((row * PADK + col) * 2),
                       A + (size_t)(mbase + row) * K + k0 + col);
            CP_ASYNC16(base + (uint32_t)((SA_H + row * PADK + col) * 2),
                       Bt + (size_t)(nbase + row) * K + k0 + col);
        }
    };

    load_stage(0, 0); CP_COMMIT();
    load_stage(1, 1); CP_COMMIT();

    const int q = lane >> 2, r4 = lane & 3;

    for (int kt = 0; kt < T; kt++) {
        CP_WAIT(1);
        __syncthreads();

        if (kt + 2 < T) load_stage(kt + 2, (kt + 2) % NSTG);
        CP_COMMIT();

        const __half* a_st = smem_h + (kt % NSTG) * STG_H;
        const __half* b_st = a_st + SA_H;

        uint32_t afr[2][4][4];
        uint32_t bfr[2][4][2];

        auto load_frag = [&](int ks, int buf) {
            const int kk = ks * 16;
            #pragma unroll
            for (int mt = 0; mt < 4; mt++) {
                const __half* ap = a_st + (warpM * 64 + mt * 16 + q) * PADK + kk + 2 * r4;
                afr[buf][mt][0] = *(const uint32_t*)(ap);
                afr[buf][mt][1] = *(const uint32_t*)(ap + 8 * PADK);
                afr[buf][mt][2] = *(const uint32_t*)(ap + 8);
                afr[buf][mt][3] = *(const uint32_t*)(ap + 8 * PADK + 8);
            }
            #pragma unroll
            for (int nt = 0; nt < 4; nt++) {
                const __half* bp = b_st + (warpN * 32 + nt * 8 + q) * PADK + kk + 2 * r4;
                bfr[buf][nt][0] = *(const uint32_t*)(bp);
                bfr[buf][nt][1] = *(const uint32_t*)(bp + 8);
            }
        };

        load_frag(0, 0);
        #pragma unroll
        for (int ks = 0; ks < 4; ks++) {
            if (ks < 3) load_frag(ks + 1, (ks + 1) & 1);
            const int b = ks & 1;
            #pragma unroll
            for (int mt = 0; mt < 4; mt++)
                #pragma unroll
                for (int nt = 0; nt < 4; nt++)
                    mma_f16_16n8k16(acc[mt][nt], afr[b][mt][0], afr[b][mt][1],
                                    afr[b][mt][2], afr[b][mt][3],
                                    bfr[b][nt][0], bfr[b][nt][1]);
        }
    }

    // ---- epilogue ----
    #pragma unroll
    for (int mt = 0; mt < 4; mt++) {
        #pragma unroll
        for (int nt = 0; nt < 4; nt++) {
            int col = nbase + warpN * 32 + nt * 8 + 2 * r4;
            float2 bv = *(const float2*)(bias + col);
            #pragma unroll
            for (int half_i = 0; half_i < 2; half_i++) {
                size_t row = (size_t)(mbase + warpM * 64 + mt * 16 + q + half_i * 8);
                float2 o;
                o.x = acc[mt][nt][half_i * 2 + 0] + bv.x;
                o.y = acc[mt][nt][half_i * 2 + 1] + bv.y;
                if (EPI == EPI_PHI) {
                    o.x = (o.x > 0.0f) ? o.x + 1.0f : expf(o.x);
                    o.y = (o.y > 0.0f) ? o.y + 1.0f : expf(o.y);
                } else if (EPI == EPI_GELU) {
                    o.x = gelu_tanh(o.x);
                    o.y = gelu_tanh(o.y);
                } else if (EPI == EPI_RES) {
                    float2 rv = __half22float2(*(const __half2*)(resid + row * N + col));
                    o.x += rv.x; o.y += rv.y;
                }
                if (sizeof(CT) == 2) {
                    *(__half2*)((__half*)C + row * N + col) = __floats2half2_rn(o.x, o.y);
                } else {
                    *(float2*)((float*)C + row * N + col) = o;
                }
            }
        }
    }
}

// ---------------------------------------------------------------------------
// Weight transpose W[K,N] (fp32) -> Wt[N,K] (fp16)
// ---------------------------------------------------------------------------
__global__ __launch_bounds__(256)
void transpose_kernel(const float* __restrict__ W, __half* __restrict__ Wt, int K, int N)
{
    __shared__ float tile[32][33];
    int k0 = blockIdx.x * 32, n0 = blockIdx.y * 32;
    int tx = threadIdx.x, ty = threadIdx.y;     // 32 x 8
    #pragma unroll
    for (int i = 0; i < 32; i += 8)
        tile[ty + i][tx] = W[(size_t)(k0 + ty + i) * N + n0 + tx];
    __syncthreads();
    #pragma unroll
    for (int i = 0; i < 32; i += 8)
        Wt[(size_t)(n0 + ty + i) * K + k0 + tx] = __float2half(tile[tx][ty + i]);
}

// ---------------------------------------------------------------------------
// LayerNorm: fp32 in, fp16 out
// ---------------------------------------------------------------------------
__global__ __launch_bounds__(128)
void ln_kernel(const float* __restrict__ x, const float* __restrict__ g,
               const float* __restrict__ bta, __half* __restrict__ out)
{
    __shared__ float red[4];
    size_t row = blockIdx.x;
    int t = threadIdx.x;
    int lane = t & 31, warp = t >> 5;

    float4 v = *(const float4*)(x + row * DD + t * 4);
    float s = v.x + v.y + v.z + v.w;
    #pragma unroll
    for (int o = 16; o; o >>= 1) s += __shfl_xor_sync(0xffffffffu, s, o);
    if (lane == 0) red[warp] = s;
    __syncthreads();
    float mean = (red[0] + red[1] + red[2] + red[3]) * (1.0f / DD);
    __syncthreads();

    float dx = v.x - mean, dy = v.y - mean, dz = v.z - mean, dw = v.w - mean;
    float q = dx * dx + dy * dy + dz * dz + dw * dw;
    #pragma unroll
    for (int o = 16; o; o >>= 1) q += __shfl_xor_sync(0xffffffffu, q, o);
    if (lane == 0) red[warp] = q;
    __syncthreads();
    float var = (red[0] + red[1] + red[2] + red[3]) * (1.0f / DD);
    float rs = rsqrtf(var + LN_EPS);

    float4 gv = *(const float4*)(g + t * 4);
    float4 bv = *(const float4*)(bta + t * 4);
    __half* op = out + row * DD + t * 4;
    *(__half2*)(op)     = __floats2half2_rn(dx * rs * gv.x + bv.x, dy * rs * gv.y + bv.y);
    *(__half2*)(op + 2) = __floats2half2_rn(dz * rs * gv.z + bv.z, dw * rs * gv.w + bv.w);
}

// ---------------------------------------------------------------------------
// Zero kv + ksum accumulators
// ---------------------------------------------------------------------------
__global__ void zero_acc_kernel()
{
    int idx = blockIdx.x * blockDim.x + threadIdx.x;
    const int NKV = BB * HH * DK * DV;
    const int NKS = BB * HH * DK;
    if (idx < NKV) g_kv[idx] = 0.0f;
    else if (idx < NKV + NKS) g_ksum[idx - NKV] = 0.0f;
}

// ---------------------------------------------------------------------------
// kv[b,h,d,m] = sum_n pk[b,n,h,d] * v[b,n,h,m];  ksum = sum_n pk  (fp16 in)
// ---------------------------------------------------------------------------
#define KV_CHUNK 2048
__global__ __launch_bounds__(256)
void kvred_kernel(const __half* __restrict__ pk, const __half* __restrict__ v)
{
    __shared__ float s_pk[8][64];
    __shared__ float s_v[8][64];
    const int bh = blockIdx.x;
    const int b  = bh >> 3, h = bh & 7;
    const int n0 = blockIdx.y * KV_CHUNK;
    const int t  = threadIdx.x;
    const int d0 = (t >> 4) * 4, m0 = (t & 15) * 4;
    const int ltt = t >> 5, lc2 = (t & 31) * 2;   // load coords: 8 rows x 32 half2

    float c[4][4];
    #pragma unroll
    for (int i = 0; i < 4; i++)
        #pragma unroll
        for (int j = 0; j < 4; j++) c[i][j] = 0.0f;
    float sk = 0.0f;

    const size_t base = (size_t)b * NN * DD + h * 64;
    for (int n = n0; n < n0 + KV_CHUNK; n += 8) {
        size_t off = base + (size_t)(n + ltt) * DD + lc2;
        float2 pkv = __half22float2(*(const __half2*)(pk + off));
        float2 vv  = __half22float2(*(const __half2*)(v + off));
        s_pk[ltt][lc2] = pkv.x; s_pk[ltt][lc2 + 1] = pkv.y;
        s_v [ltt][lc2] = vv.x;  s_v [ltt][lc2 + 1] = vv.y;
        __syncthreads();
        #pragma unroll
        for (int tt = 0; tt < 8; tt++) {
            float a[4], b2[4];
            *(float4*)a  = *(const float4*)(&s_pk[tt][d0]);
            *(float4*)b2 = *(const float4*)(&s_v[tt][m0]);
            #pragma unroll
            for (int i = 0; i < 4; i++)
                #pragma unroll
                for (int j = 0; j < 4; j++) c[i][j] += a[i] * b2[j];
        }
        if (t < 64) {
            #pragma unroll
            for (int tt = 0; tt < 8; tt++) sk += s_pk[tt][t];
        }
        __syncthreads();
    }

    float* kvp = g_kv + (size_t)bh * (DK * DV);
    #pragma unroll
    for (int i = 0; i < 4; i++)
        #pragma unroll
        for (int j = 0; j < 4; j++)
            atomicAdd(&kvp[(d0 + i) * DV + m0 + j], c[i][j]);
    if (t < 64) atomicAdd(&g_ksum[bh * DK + t], sk);
}

// ---------------------------------------------------------------------------
// attention apply: block = 64 tokens x (b,h); smem mini-GEMM 64x64x64
// fp16 in (pq), fp16 out (attn)
// ---------------------------------------------------------------------------
__global__ __launch_bounds__(256)
void attn_kernel(const __half* __restrict__ pq, __half* __restrict__ out)
{
    __shared__ float s_kv[64 * 64];
    __shared__ float s_q[64][65];
    __shared__ float s_z[64];
    const int bh = blockIdx.y;
    const int b = bh >> 3, h = bh & 7;
    const int n0 = blockIdx.x << 6;
    const int t = threadIdx.x;

    const float* kvp = g_kv + (size_t)bh * 4096;
    #pragma unroll
    for (int i = 0; i < 16; i++) s_kv[t + i * 256] = kvp[t + i * 256];

    const size_t qbase = ((size_t)b * NN + n0) * DD + h * 64;
    #pragma unroll
    for (int i = 0; i < 8; i++) {
        int idx = t + i * 256;           // 0..2047 half2
        int r = idx >> 5, c2 = (idx & 31) * 2;
        float2 qv = __half22float2(*(const __half2*)(pq + qbase + (size_t)r * DD + c2));
        s_q[r][c2] = qv.x; s_q[r][c2 + 1] = qv.y;
    }
    __syncthreads();

    if (t < 64) {
        const float* ks = g_ksum + bh * 64;
        float dot = 0.0f;
        #pragma unroll
        for (int d = 0; d < 64; d++) dot += s_q[t][d] * ks[d];
        s_z[t] = 1.0f / (dot + ATTN_EPS);
    }
    __syncthreads();

    const int i4 = (t >> 4) << 2;
    const int j4 = (t & 15) << 2;
    float acc[4][4] = {};
    #pragma unroll
    for (int d = 0; d < 64; d++) {
        float bvec[4];
        *(float4*)bvec = *(const float4*)(&s_kv[d * 64 + j4]);
        #pragma unroll
        for (int r = 0; r < 4; r++) {
            float a = s_q[i4 + r][d];
            acc[r][0] += a * bvec[0];
            acc[r][1] += a * bvec[1];
            acc[r][2] += a * bvec[2];
            acc[r][3] += a * bvec[3];
        }
    }
    #pragma unroll
    for (int r = 0; r < 4; r++) {
        float z = s_z[i4 + r];
        __half* op = out + ((size_t)b * NN + n0 + i4 + r) * DD + h * 64 + j4;
        *(__half2*)(op)     = __floats2half2_rn(acc[r][0] * z, acc[r][1] * z);
        *(__half2*)(op + 2) = __floats2half2_rn(acc[r][2] * z, acc[r][3] * z);
    }
}

// ---------------------------------------------------------------------------
// Launch
// ---------------------------------------------------------------------------
extern "C" void kernel_launch(void* const* d_in, const int* in_sizes, int n_in,
                              void* d_out, int out_size)
{
    const float* x     = (const float*)d_in[0];
    const float* ln1_g = (const float*)d_in[1];
    const float* ln1_b = (const float*)d_in[2];
    const float* Wq    = (const float*)d_in[3];
    const float* bq    = (const float*)d_in[4];
    const float* Wk    = (const float*)d_in[5];
    const float* bk    = (const float*)d_in[6];
    const float* Wv    = (const float*)d_in[7];
    const float* bv    = (const float*)d_in[8];
    const float* Wo    = (const float*)d_in[9];
    const float* bo    = (const float*)d_in[10];
    const float* ln2_g = (const float*)d_in[11];
    const float* ln2_b = (const float*)d_in[12];
    const float* W1    = (const float*)d_in[13];
    const float* b1    = (const float*)d_in[14];
    const float* W2    = (const float*)d_in[15];
    const float* b2    = (const float*)d_in[16];
    float* out = (float*)d_out;

    __half *p_h, *p_pq, *p_pk, *p_v, *p_attn, *p_h2, *p_act;
    __half *p_wqt, *p_wkt, *p_wvt, *p_wot, *p_w1t, *p_w2t;
    float *p_hres;
    cudaGetSymbolAddress((void**)&p_h,    g_h);
    cudaGetSymbolAddress((void**)&p_pq,   g_pq);
    cudaGetSymbolAddress((void**)&p_pk,   g_pk);
    cudaGetSymbolAddress((void**)&p_v,    g_v);
    cudaGetSymbolAddress((void**)&p_attn, g_attn);
    cudaGetSymbolAddress((void**)&p_hres, g_hres);
    cudaGetSymbolAddress((void**)&p_h2,   g_h2);
    cudaGetSymbolAddress((void**)&p_act,  g_act);
    cudaGetSymbolAddress((void**)&p_wqt,  g_wqt);
    cudaGetSymbolAddress((void**)&p_wkt,  g_wkt);
    cudaGetSymbolAddress((void**)&p_wvt,  g_wvt);
    cudaGetSymbolAddress((void**)&p_wot,  g_wot);
    cudaGetSymbolAddress((void**)&p_w1t,  g_w1t);
    cudaGetSymbolAddress((void**)&p_w2t,  g_w2t);

    cudaFuncSetAttribute(mgemm_kernel<EPI_PHI , __half>, cudaFuncAttributeMaxDynamicSharedMemorySize, GEMM_SMEM);
    cudaFuncSetAttribute(mgemm_kernel<EPI_BIAS, __half>, cudaFuncAttributeMaxDynamicSharedMemorySize, GEMM_SMEM);
    cudaFuncSetAttribute(mgemm_kernel<EPI_GELU, __half>, cudaFuncAttributeMaxDynamicSharedMemorySize, GEMM_SMEM);
    cudaFuncSetAttribute(mgemm_kernel<EPI_RES , float >, cudaFuncAttributeMaxDynamicSharedMemorySize, GEMM_SMEM);

    // 0. weight transposes (fp16, K-major)
    transpose_kernel<<<dim3(DD / 32, DD / 32),  dim3(32, 8)>>>(Wq, p_wqt, DD, DD);
    transpose_kernel<<<dim3(DD / 32, DD / 32),  dim3(32, 8)>>>(Wk, p_wkt, DD, DD);
    transpose_kernel<<<dim3(DD / 32, DD / 32),  dim3(32, 8)>>>(Wv, p_wvt, DD, DD);
    transpose_kernel<<<dim3(DD / 32, DD / 32),  dim3(32, 8)>>>(Wo, p_wot, DD, DD);
    transpose_kernel<<<dim3(DD / 32, HID / 32), dim3(32, 8)>>>(W1, p_w1t, DD, HID);
    transpose_kernel<<<dim3(HID / 32, DD / 32), dim3(32, 8)>>>(W2, p_w2t, HID, DD);

    // 1. LN1
    ln_kernel<<<NTOK, 128>>>(x, ln1_g, ln1_b, p_h);

    // 2-4. Q, K, V projections (fp16 tensor cores; phi fused on q,k)
    {
        dim3 grid(DD / 128, NTOK / 128);
        mgemm_kernel<EPI_PHI , __half><<<grid, 256, GEMM_SMEM>>>(p_h, p_wqt, bq, nullptr, p_pq, DD, DD);
        mgemm_kernel<EPI_PHI , __half><<<grid, 256, GEMM_SMEM>>>(p_h, p_wkt, bk, nullptr, p_pk, DD, DD);
        mgemm_kernel<EPI_BIAS, __half><<<grid, 256, GEMM_SMEM>>>(p_h, p_wvt, bv, nullptr, p_v,  DD, DD);
    }

    // 5. zero accumulators
    zero_acc_kernel<<<(BB * HH * DK * DV + BB * HH * DK + 255) / 256, 256>>>();

    // 6. kv / ksum reduction
    kvred_kernel<<<dim3(BB * HH, NN / KV_CHUNK), 256>>>(p_pk, p_v);

    // 7. attention apply
    attn_kernel<<<dim3(NN / 64, BB * HH), 256>>>(p_pq, p_attn);

    // 8. output projection + residual -> hres (fp32)
    mgemm_kernel<EPI_RES, float><<<dim3(DD / 128, NTOK / 128), 256, GEMM_SMEM>>>(
        p_attn, p_wot, bo, p_h, p_hres, DD, DD);

    // 9. LN2
    ln_kernel<<<NTOK, 128>>>(p_hres, ln2_g, ln2_b, p_h2);

    // 10. MLP up + gelu
    mgemm_kernel<EPI_GELU, __half><<<dim3(HID / 128, NTOK / 128), 256, GEMM_SMEM>>>(
        p_h2, p_w1t, b1, nullptr, p_act, HID, DD);

    // 11. MLP down + residual -> out (fp32)
    mgemm_kernel<EPI_RES, float><<<dim3(DD / 128, NTOK / 128), 256, GEMM_SMEM>>>(
        p_act, p_w2t, b2, p_h2, out, DD, HID);
}